// round 8
// baseline (speedup 1.0000x reference)
#include <cuda_runtime.h>
#include <math.h>
#include <stdint.h>

#define EPS 1e-5f
constexpr int NN   = 8192;
constexpr int IND  = 343;
constexpr int HIDD = 1000;
constexpr int HPAD = 1024;
constexpr int OUTD = 4;

// Scratch (allocation-free rule)
__device__ float g_xw[(size_t)NN * HPAD];   // X@W1 (raw fp32, padded cols zero)
__device__ float g_xwT[(size_t)HPAD * NN];  // transposed, RNA-rounded, k-permuted
__device__ float g_h1[(size_t)NN * HPAD];   // relu(adj@xw + b1)
__device__ float g_b1p[HPAD];

// ---------------------------------------------------------------------------
// helpers (base PTX only)
// ---------------------------------------------------------------------------
__device__ __forceinline__ uint32_t f2tf32(float v) {
    uint32_t r; asm("cvt.rna.tf32.f32 %0, %1;" : "=r"(r) : "f"(v)); return r;
}
__device__ __forceinline__ float rna_f(float v) { return __uint_as_float(f2tf32(v)); }

__device__ __forceinline__ void cp_async16(uint32_t dst, const void* src) {
    asm volatile("cp.async.cg.shared.global [%0], [%1], 16;\n" :: "r"(dst), "l"(src));
}
__device__ __forceinline__ void cp_async16b(uint32_t dst, const void* src, int bytes) {
    asm volatile("cp.async.cg.shared.global [%0], [%1], 16, %2;\n" :: "r"(dst), "l"(src), "r"(bytes));
}
__device__ __forceinline__ void cp_async4(uint32_t dst, const void* src, int bytes) {
    asm volatile("cp.async.ca.shared.global [%0], [%1], 4, %2;\n" :: "r"(dst), "l"(src), "r"(bytes));
}
__device__ __forceinline__ void cp_commit() {
    asm volatile("cp.async.commit_group;\n" ::: "memory");
}
#define CP_WAIT(n) asm volatile("cp.async.wait_group %0;\n" :: "n"(n) : "memory")

__device__ __forceinline__ void mma_tf32(float* d, const uint32_t* a, const uint32_t* b) {
    asm volatile(
        "mma.sync.aligned.m16n8k8.row.col.f32.tf32.tf32.f32 "
        "{%0,%1,%2,%3}, {%4,%5,%6,%7}, {%8,%9}, {%0,%1,%2,%3};"
        : "+f"(d[0]), "+f"(d[1]), "+f"(d[2]), "+f"(d[3])
        : "r"(a[0]), "r"(a[1]), "r"(a[2]), "r"(a[3]), "r"(b[0]), "r"(b[1]));
}

// ---------------------------------------------------------------------------
// GEMM2: h1 = relu(adj @ xw + b1)   [M=8192, N=1024, K=8192]
// CTA 128m x 256n, BK=32, 512 threads = 16 warps in 4m x 4n grid,
// warp tile 32x64 (mi=2, ni=8). 3-stage combined cp.async pipeline, one
// barrier per ktile. A stored raw (cvt.rna at frag load), B pre-rounded
// + k-permuted (LDS.64 frags).
// ---------------------------------------------------------------------------
constexpr int LDA_S = 36;
constexpr int LDB_S = 40;
constexpr int A_STG = 128 * LDA_S;             // 4608 floats
constexpr int B_STG = 256 * LDB_S;             // 10240 floats
constexpr int STG   = A_STG + B_STG;           // 14848 floats
constexpr int G2_SMEM = 3 * STG * 4;           // 178176 B
constexpr int KT2 = NN / 32;                   // 256

__global__ __launch_bounds__(512, 1)
void gemm2_mma(const float* __restrict__ adj,
               const float* __restrict__ xwT,
               const float* __restrict__ bias,
               float* __restrict__ C)
{
    extern __shared__ float smf[];
    const uint32_t smb = (uint32_t)__cvta_generic_to_shared(smf);
    const int tid  = threadIdx.x;
    const int lane = tid & 31;
    const int wid  = tid >> 5;
    const int wm   = (wid & 3) * 32;           // 4 m-warps
    const int wn   = (wid >> 2) * 64;          // 4 n-warps
    const int r    = lane >> 2;
    const int c4   = lane & 3;
    const int m0   = blockIdx.y * 128;
    const int n0   = blockIdx.x * 256;

    const float* Abase = adj + (size_t)m0 * NN;
    const float* Bbase = xwT + (size_t)n0 * NN;

    float acc[2][8][4];
    #pragma unroll
    for (int i = 0; i < 2; i++)
        #pragma unroll
        for (int j = 0; j < 8; j++)
            #pragma unroll
            for (int q = 0; q < 4; q++) acc[i][j][q] = 0.f;

    // cp.async source/dest precompute:
    //  A tile: 1024 16B-chunks, 2 per thread. B tile: 2048 chunks, 4 per thread.
    const int arow0 = tid >> 3,            apos = tid & 7;          // chunks tid, tid+512
    const int brow0 = tid >> 3,            bpos = tid & 7;          // chunks tid + c*512

    auto cpAB = [&](int kt, int s) {
        const uint32_t sa = smb + (uint32_t)(s * STG) * 4;
        const uint32_t sb = sa + (uint32_t)A_STG * 4;
        const float* Ak = Abase + kt * 32;
        const float* Bk = Bbase + kt * 32;
        #pragma unroll
        for (int c = 0; c < 2; c++) {
            int row = arow0 + c * 64;
            cp_async16(sa + (uint32_t)(row * LDA_S + apos * 4) * 4,
                       Ak + (size_t)row * NN + apos * 4);
        }
        #pragma unroll
        for (int c = 0; c < 4; c++) {
            int row = brow0 + c * 64;
            cp_async16(sb + (uint32_t)(row * LDB_S + bpos * 4) * 4,
                       Bk + (size_t)row * NN + bpos * 4);
        }
        cp_commit();
    };

    // ---- prologue ----
    cpAB(0, 0);
    cpAB(1, 1);

    for (int kt = 0; kt < KT2; kt++) {
        if (kt + 1 < KT2) { CP_WAIT(1); } else { CP_WAIT(0); }
        __syncthreads();
        if (kt + 2 < KT2) cpAB(kt + 2, (kt + 2) % 3);

        const float* As = smf + (kt % 3) * STG;
        const float* Bf = As + A_STG;

        #pragma unroll
        for (int g = 0; g < 4; g++) {
            const int kk = g * 8;
            uint32_t a[2][4], b[8][2];
            #pragma unroll
            for (int mi = 0; mi < 2; mi++) {
                int base = (wm + mi * 16 + r) * LDA_S + kk + c4;
                a[mi][0] = f2tf32(As[base]);
                a[mi][1] = f2tf32(As[base + 8 * LDA_S]);
                a[mi][2] = f2tf32(As[base + 4]);
                a[mi][3] = f2tf32(As[base + 8 * LDA_S + 4]);
            }
            #pragma unroll
            for (int ni = 0; ni < 8; ni++) {
                float2 v = *(const float2*)(Bf + (wn + ni * 8 + r) * LDB_S + kk + 2 * c4);
                b[ni][0] = __float_as_uint(v.x);
                b[ni][1] = __float_as_uint(v.y);
            }
            #pragma unroll
            for (int mi = 0; mi < 2; mi++)
                #pragma unroll
                for (int ni = 0; ni < 8; ni++)
                    mma_tf32(acc[mi][ni], a[mi], b[ni]);
        }
    }

    // epilogue: bias + relu
    #pragma unroll
    for (int mi = 0; mi < 2; mi++) {
        #pragma unroll
        for (int h = 0; h < 2; h++) {
            int row = m0 + wm + mi * 16 + r + h * 8;
            float* dst = C + (size_t)row * HPAD + n0 + wn;
            #pragma unroll
            for (int ni = 0; ni < 8; ni++) {
                int col = ni * 8 + c4 * 2;
                float2 v;
                v.x = fmaxf(acc[mi][ni][h * 2 + 0] + bias[n0 + wn + col],     0.f);
                v.y = fmaxf(acc[mi][ni][h * 2 + 1] + bias[n0 + wn + col + 1], 0.f);
                *(float2*)(dst + col) = v;
            }
        }
    }
}

// ---------------------------------------------------------------------------
// GEMM1 (proven): xw = feat @ W1  [tf32 HMMA, K=343]
// ---------------------------------------------------------------------------
constexpr int BM = 128, BN = 128, BK = 32;
constexpr int LDAS = 36, LDBS = 136;
constexpr int A_SZ = BM * LDAS, B_SZ = BK * LDBS;
constexpr int STAGE = A_SZ + B_SZ;
constexpr int G1_SMEM = 2 * STAGE * 4;

__global__ __launch_bounds__(256, 1)
void gemm1_hmma(const float* __restrict__ A, const float* __restrict__ B,
                float* __restrict__ C, int M, int N, int K, int lda, int ldb, int ldc)
{
    extern __shared__ float sm[];
    const int tid = threadIdx.x, lane = tid & 31, wid = tid >> 5;
    const int wm0 = (wid & 1) * 64, wn0 = (wid >> 1) * 32;
    const int m0 = blockIdx.y * BM, n0 = blockIdx.x * BN;
    const uint32_t smbase = (uint32_t)__cvta_generic_to_shared(sm);

    float acc[4][4][4];
    #pragma unroll
    for (int i = 0; i < 4; i++)
        #pragma unroll
        for (int j = 0; j < 4; j++)
            #pragma unroll
            for (int q = 0; q < 4; q++) acc[i][j][q] = 0.f;

    auto loadA = [&](int kt, int s) {
        const int k0 = kt * BK;
        #pragma unroll
        for (int t = 0; t < 16; t++) {
            int id = tid + t * 256;
            int m = id >> 5, c = id & 31;
            int gk = k0 + c;
            int bytes = (gk < K) ? 4 : 0;
            const float* src = bytes ? (A + (size_t)(m0 + m) * lda + gk) : A;
            cp_async4(smbase + (uint32_t)(s * STAGE + m * LDAS + c) * 4, src, bytes);
        }
    };
    auto loadB = [&](int kt, int s) {
        const int k0 = kt * BK;
        #pragma unroll
        for (int t = 0; t < 4; t++) {
            int id = tid + t * 256;
            int k = id >> 5, c = id & 31;
            int gk = k0 + k, gn = n0 + c * 4;
            int bytes = 0;
            if (gk < K) { bytes = (N - gn) * 4; bytes = bytes < 0 ? 0 : (bytes > 16 ? 16 : bytes); }
            const float* src = bytes ? (B + (size_t)gk * ldb + gn) : B;
            cp_async16b(smbase + (uint32_t)(s * STAGE + A_SZ + k * LDBS + c * 4) * 4, src, bytes);
        }
    };

    const int KT = (K + BK - 1) / BK;
    const int r = lane >> 2, c4 = lane & 3;
    loadA(0, 0); loadB(0, 0); cp_commit();

    for (int kt = 0; kt < KT; kt++) {
        if (kt + 1 < KT) {
            loadA(kt + 1, (kt + 1) & 1);
            loadB(kt + 1, (kt + 1) & 1);
            cp_commit();
            CP_WAIT(1);
        } else {
            CP_WAIT(0);
        }
        __syncthreads();
        const float* As  = sm + (kt & 1) * STAGE;
        const float* Bsm = As + A_SZ;
        #pragma unroll
        for (int kk4 = 0; kk4 < 4; kk4++) {
            const int kk = kk4 * 8;
            uint32_t a[4][4], b[4][2];
            #pragma unroll
            for (int mi = 0; mi < 4; mi++) {
                int base = (wm0 + mi * 16 + r) * LDAS + kk + c4;
                a[mi][0] = f2tf32(As[base]);
                a[mi][1] = f2tf32(As[base + 8 * LDAS]);
                a[mi][2] = f2tf32(As[base + 4]);
                a[mi][3] = f2tf32(As[base + 8 * LDAS + 4]);
            }
            #pragma unroll
            for (int ni = 0; ni < 4; ni++) {
                int bb = (kk + c4) * LDBS + wn0 + ni * 8 + r;
                b[ni][0] = f2tf32(Bsm[bb]);
                b[ni][1] = f2tf32(Bsm[bb + 4 * LDBS]);
            }
            #pragma unroll
            for (int mi = 0; mi < 4; mi++)
                #pragma unroll
                for (int ni = 0; ni < 4; ni++)
                    mma_tf32(acc[mi][ni], a[mi], b[ni]);
        }
        __syncthreads();
    }

    #pragma unroll
    for (int mi = 0; mi < 4; mi++)
        #pragma unroll
        for (int ni = 0; ni < 4; ni++) {
            int row0 = m0 + wm0 + mi * 16 + r;
            int col0 = n0 + wn0 + ni * 8 + c4 * 2;
            #pragma unroll
            for (int h = 0; h < 2; h++) {
                int row = row0 + h * 8;
                #pragma unroll
                for (int q = 0; q < 2; q++) {
                    int col = col0 + q;
                    if (col < N) C[(size_t)row * ldc + col] = acc[mi][ni][h * 2 + q];
                }
            }
        }
}

// ---------------------------------------------------------------------------
// transpose + RNA round + k-permute: xw[8192][1024] -> xwT[1024][8192]
// ---------------------------------------------------------------------------
__global__ void transpose_rna_perm(const float* __restrict__ in,
                                   float* __restrict__ out)
{
    __shared__ float t[32][33];
    int x  = blockIdx.x * 32 + threadIdx.x;
    int y0 = blockIdx.y * 32;
    #pragma unroll
    for (int j = threadIdx.y; j < 32; j += 8)
        t[j][threadIdx.x] = in[(size_t)(y0 + j) * HPAD + x];
    __syncthreads();
    int k  = y0 + threadIdx.x;
    int o  = k & 7;
    int kp = (k & ~7) | ((o < 4) ? (2 * o) : (2 * (o - 4) + 1));
    int n0 = blockIdx.x * 32;
    #pragma unroll
    for (int j = threadIdx.y; j < 32; j += 8)
        out[(size_t)(n0 + j) * NN + kp] = rna_f(t[threadIdx.x][j]);
}

__global__ void pad_bias_kernel(const float* __restrict__ b1, float* __restrict__ b1p) {
    int i = threadIdx.x;
    b1p[i] = (i < HIDD) ? b1[i] : 0.f;
}

// ---------------------------------------------------------------------------
// LayerNorm(1000) + head, one warp per row.
// ---------------------------------------------------------------------------
__global__ __launch_bounds__(256)
void ln_head_kernel(const float* __restrict__ h,
                    const float* __restrict__ gamma,
                    const float* __restrict__ beta,
                    const float* __restrict__ Wm,
                    const float* __restrict__ bm,
                    float* __restrict__ out)
{
    const int row  = blockIdx.x * 8 + threadIdx.y;
    if (row >= NN) return;
    const int lane = threadIdx.x;
    const float* hr = h + (size_t)row * HPAD;

    float v[32];
    float s = 0.f, ss = 0.f;
    #pragma unroll
    for (int i = 0; i < 32; i++) {
        int n = lane + 32 * i;
        float x = (n < HIDD) ? hr[n] : 0.f;
        v[i] = x; s += x; ss += x * x;
    }
    #pragma unroll
    for (int off = 16; off > 0; off >>= 1) {
        s  += __shfl_xor_sync(0xFFFFFFFF, s,  off);
        ss += __shfl_xor_sync(0xFFFFFFFF, ss, off);
    }
    const float mu   = s * (1.0f / HIDD);
    const float var  = ss * (1.0f / HIDD) - mu * mu;
    const float rinv = rsqrtf(var + EPS);

    float acc[OUTD] = {0.f, 0.f, 0.f, 0.f};
    #pragma unroll
    for (int i = 0; i < 32; i++) {
        int n = lane + 32 * i;
        if (n < HIDD) {
            float xn = (v[i] - mu) * rinv * gamma[n] + beta[n];
            #pragma unroll
            for (int o = 0; o < OUTD; o++)
                acc[o] = fmaf(xn, Wm[n * OUTD + o], acc[o]);
        }
    }
    #pragma unroll
    for (int o = 0; o < OUTD; o++) {
        #pragma unroll
        for (int off = 16; off > 0; off >>= 1)
            acc[o] += __shfl_xor_sync(0xFFFFFFFF, acc[o], off);
    }
    if (lane == 0) {
        #pragma unroll
        for (int o = 0; o < OUTD; o++)
            out[(size_t)row * OUTD + o] = acc[o] + bm[o];
    }
}

// ---------------------------------------------------------------------------
extern "C" void kernel_launch(void* const* d_in, const int* in_sizes, int n_in,
                              void* d_out, int out_size)
{
    const float* adj   = (const float*)d_in[0];
    const float* feat  = (const float*)d_in[1];
    const float* W1    = (const float*)d_in[2];
    const float* b1    = (const float*)d_in[3];
    const float* gamma = (const float*)d_in[4];
    const float* beta  = (const float*)d_in[5];
    const float* Wm    = (const float*)d_in[6];
    const float* bm    = (const float*)d_in[7];
    float* out = (float*)d_out;

    float *xw, *xwT, *h1, *b1p;
    cudaGetSymbolAddress((void**)&xw,  g_xw);
    cudaGetSymbolAddress((void**)&xwT, g_xwT);
    cudaGetSymbolAddress((void**)&h1,  g_h1);
    cudaGetSymbolAddress((void**)&b1p, g_b1p);

    cudaFuncSetAttribute(gemm1_hmma, cudaFuncAttributeMaxDynamicSharedMemorySize, G1_SMEM);
    cudaFuncSetAttribute(gemm2_mma,  cudaFuncAttributeMaxDynamicSharedMemorySize, G2_SMEM);

    cudaMemsetAsync(xw, 0, (size_t)NN * HPAD * sizeof(float));
    pad_bias_kernel<<<1, HPAD>>>(b1, b1p);

    // GEMM1: xw = feat @ W1
    {
        dim3 grid((HIDD + BN - 1) / BN, NN / BM);
        gemm1_hmma<<<grid, 256, G1_SMEM>>>(feat, W1, xw, NN, HIDD, IND, IND, HIDD, HPAD);
    }

    // xwT = RNA(xw)^T with k-permute
    {
        dim3 block(32, 8), grid(HPAD / 32, NN / 32);
        transpose_rna_perm<<<grid, block>>>(xw, xwT);
    }

    // GEMM2: h1 = relu(adj @ xw + b1)
    {
        dim3 grid(HPAD / 256, NN / 128);
        gemm2_mma<<<grid, 512, G2_SMEM>>>(adj, xwT, b1p, h1);
    }

    // LayerNorm + head
    {
        dim3 block(32, 8);
        ln_head_kernel<<<NN / 8, block>>>(h1, gamma, beta, Wm, bm, out);
    }
}

// round 9
// speedup vs baseline: 2.1094x; 2.1094x over previous
#include <cuda_runtime.h>
#include <math.h>
#include <stdint.h>

#define EPS 1e-5f
constexpr int NN   = 8192;
constexpr int IND  = 343;
constexpr int NPAD = 384;    // padded IND for GEMM_A tiles
constexpr int HIDD = 1000;
constexpr int HPAD = 1024;
constexpr int OUTD = 4;

// Scratch (allocation-free rule)
__device__ float g_featT[(size_t)NPAD * NN];  // feat^T, RNA-rounded, k-permuted, zero-padded rows
__device__ float g_Y[(size_t)NN * NPAD];      // adj @ feat
__device__ float g_h1[(size_t)NN * HPAD];     // relu(Y @ W1 + b1)

// ---------------------------------------------------------------------------
// helpers (base PTX only — sm_100 target has no tcgen05)
// ---------------------------------------------------------------------------
__device__ __forceinline__ uint32_t f2tf32(float v) {
    uint32_t r; asm("cvt.rna.tf32.f32 %0, %1;" : "=r"(r) : "f"(v)); return r;
}
__device__ __forceinline__ float rna_f(float v) { return __uint_as_float(f2tf32(v)); }

__device__ __forceinline__ void cp_async16(uint32_t dst, const void* src) {
    asm volatile("cp.async.cg.shared.global [%0], [%1], 16;\n" :: "r"(dst), "l"(src));
}
__device__ __forceinline__ void cp_async16b(uint32_t dst, const void* src, int bytes) {
    asm volatile("cp.async.cg.shared.global [%0], [%1], 16, %2;\n" :: "r"(dst), "l"(src), "r"(bytes));
}
__device__ __forceinline__ void cp_commit() {
    asm volatile("cp.async.commit_group;\n" ::: "memory");
}
#define CP_WAIT(n) asm volatile("cp.async.wait_group %0;\n" :: "n"(n) : "memory")

__device__ __forceinline__ void mma_tf32(float* d, const uint32_t* a, const uint32_t* b) {
    asm volatile(
        "mma.sync.aligned.m16n8k8.row.col.f32.tf32.tf32.f32 "
        "{%0,%1,%2,%3}, {%4,%5,%6,%7}, {%8,%9}, {%0,%1,%2,%3};"
        : "+f"(d[0]), "+f"(d[1]), "+f"(d[2]), "+f"(d[3])
        : "r"(a[0]), "r"(a[1]), "r"(a[2]), "r"(a[3]), "r"(b[0]), "r"(b[1]));
}

// ---------------------------------------------------------------------------
// GEMM_A: Y[8192, 384] = adj[8192, 8192] @ featT^T    (tf32 HMMA)
// Tile 64m x 384n, 512 threads = 16 warps (4m x 4n), warp tile 16m x 96n
// (mi=1, ni=12). 2-stage cp.async double buffer, one barrier per ktile.
// adj raw fp32 (cvt.rna at frag load); featT pre-rounded + k-permuted.
// grid = 128 CTAs -> single wave on 148 SMs.
// ---------------------------------------------------------------------------
constexpr int GA_LDA = 36;
constexpr int GA_LDB = 40;
constexpr int GA_ASTG = 64 * GA_LDA;            // 2304 floats
constexpr int GA_BSTG = NPAD * GA_LDB;          // 15360 floats
constexpr int GA_STG  = GA_ASTG + GA_BSTG;      // 17664 floats
constexpr int GA_SMEM = 2 * GA_STG * 4;         // 141312 B
constexpr int GA_KT   = NN / 32;                // 256

__global__ __launch_bounds__(512, 1)
void gemmA(const float* __restrict__ adj,
           const float* __restrict__ featT,
           float* __restrict__ Y)
{
    extern __shared__ float smf[];
    const uint32_t smb = (uint32_t)__cvta_generic_to_shared(smf);
    const int tid  = threadIdx.x;
    const int lane = tid & 31;
    const int wid  = tid >> 5;
    const int wm   = (wid & 3) * 16;            // 4 m-warps x 16 rows
    const int wn   = (wid >> 2) * 96;           // 4 n-warps x 96 cols
    const int r    = lane >> 2;
    const int c4   = lane & 3;
    const int m0   = blockIdx.x * 64;

    const float* Abase = adj + (size_t)m0 * NN;

    float acc[12][4];
    #pragma unroll
    for (int j = 0; j < 12; j++)
        #pragma unroll
        for (int q = 0; q < 4; q++) acc[j][q] = 0.f;

    const int arow = tid >> 3;                  // 0..63
    const int apos = tid & 7;                   // 0..7

    auto cpAB = [&](int kt, int s) {
        const uint32_t sa = smb + (uint32_t)(s * GA_STG) * 4;
        const uint32_t sb = sa + (uint32_t)GA_ASTG * 4;
        const float* Ak = Abase + kt * 32;
        const float* Bk = featT + kt * 32;
        // A: 512 16B-chunks, 1 per thread
        cp_async16(sa + (uint32_t)(arow * GA_LDA + apos * 4) * 4,
                   Ak + (size_t)arow * NN + apos * 4);
        // B: 3072 chunks, 6 per thread
        #pragma unroll
        for (int c = 0; c < 6; c++) {
            int row = arow + c * 64;            // 0..383
            cp_async16(sb + (uint32_t)(row * GA_LDB + apos * 4) * 4,
                       Bk + (size_t)row * NN + apos * 4);
        }
        cp_commit();
    };

    cpAB(0, 0);

    for (int kt = 0; kt < GA_KT; kt++) {
        CP_WAIT(0);
        __syncthreads();
        if (kt + 1 < GA_KT) cpAB(kt + 1, (kt + 1) & 1);

        const float* As = smf + (kt & 1) * GA_STG;
        const float* Bf = As + GA_ASTG;

        #pragma unroll
        for (int g = 0; g < 4; g++) {
            const int kk = g * 8;
            uint32_t a[4], b[12][2];
            {
                int base = (wm + r) * GA_LDA + kk + c4;
                a[0] = f2tf32(As[base]);
                a[1] = f2tf32(As[base + 8 * GA_LDA]);
                a[2] = f2tf32(As[base + 4]);
                a[3] = f2tf32(As[base + 8 * GA_LDA + 4]);
            }
            #pragma unroll
            for (int ni = 0; ni < 12; ni++) {
                float2 v = *(const float2*)(Bf + (wn + ni * 8 + r) * GA_LDB + kk + 2 * c4);
                b[ni][0] = __float_as_uint(v.x);
                b[ni][1] = __float_as_uint(v.y);
            }
            #pragma unroll
            for (int ni = 0; ni < 12; ni++)
                mma_tf32(acc[ni], a, b[ni]);
        }
    }

    // epilogue: Y row-major, ldc = NPAD
    #pragma unroll
    for (int h = 0; h < 2; h++) {
        int row = m0 + wm + r + h * 8;
        float* dst = Y + (size_t)row * NPAD + wn;
        #pragma unroll
        for (int ni = 0; ni < 12; ni++) {
            int col = ni * 8 + c4 * 2;
            float2 v;
            v.x = acc[ni][h * 2 + 0];
            v.y = acc[ni][h * 2 + 1];
            *(float2*)(dst + col) = v;
        }
    }
}

// ---------------------------------------------------------------------------
// GEMM_B: h1 = relu(Y @ W1 + b1)   [M=8192, N=1000, K=343]
// BM=BN=128, BK=32, 256 threads, warp 64x32 (proven R3 structure),
// 16B cp.async A path (Y rows 384 floats, aligned), fused bias + ReLU.
// ---------------------------------------------------------------------------
constexpr int BM = 128, BN = 128, BK = 32;
constexpr int LDAS = 36, LDBS = 136;
constexpr int A_SZ = BM * LDAS, B_SZ = BK * LDBS;
constexpr int STAGE = A_SZ + B_SZ;
constexpr int GB_SMEM = 2 * STAGE * 4;

__global__ __launch_bounds__(256, 1)
void gemmB(const float* __restrict__ A, const float* __restrict__ B,
           const float* __restrict__ bias, float* __restrict__ C,
           int M, int N, int K, int lda, int ldb, int ldc)
{
    extern __shared__ float sm[];
    const int tid = threadIdx.x, lane = tid & 31, wid = tid >> 5;
    const int wm0 = (wid & 1) * 64, wn0 = (wid >> 1) * 32;
    const int m0 = blockIdx.y * BM, n0 = blockIdx.x * BN;
    const uint32_t smbase = (uint32_t)__cvta_generic_to_shared(sm);

    float acc[4][4][4];
    #pragma unroll
    for (int i = 0; i < 4; i++)
        #pragma unroll
        for (int j = 0; j < 4; j++)
            #pragma unroll
            for (int q = 0; q < 4; q++) acc[i][j][q] = 0.f;

    auto loadA = [&](int kt, int s) {
        const int k0 = kt * BK;
        #pragma unroll
        for (int t = 0; t < 4; t++) {
            int id = tid + t * 256;             // 1024 chunks: 128 rows x 8
            int m = id >> 3, c = id & 7;
            int gk = k0 + c * 4;
            int bytes = (K - gk) * 4;
            bytes = bytes < 0 ? 0 : (bytes > 16 ? 16 : bytes);
            const float* src = bytes ? (A + (size_t)(m0 + m) * lda + gk) : A;
            cp_async16b(smbase + (uint32_t)(s * STAGE + m * LDAS + c * 4) * 4, src, bytes);
        }
    };
    auto loadB = [&](int kt, int s) {
        const int k0 = kt * BK;
        #pragma unroll
        for (int t = 0; t < 4; t++) {
            int id = tid + t * 256;
            int k = id >> 5, c = id & 31;
            int gk = k0 + k, gn = n0 + c * 4;
            int bytes = 0;
            if (gk < K) { bytes = (N - gn) * 4; bytes = bytes < 0 ? 0 : (bytes > 16 ? 16 : bytes); }
            const float* src = bytes ? (B + (size_t)gk * ldb + gn) : B;
            cp_async16b(smbase + (uint32_t)(s * STAGE + A_SZ + k * LDBS + c * 4) * 4, src, bytes);
        }
    };

    const int KT = (K + BK - 1) / BK;
    const int r = lane >> 2, c4 = lane & 3;
    loadA(0, 0); loadB(0, 0); cp_commit();

    for (int kt = 0; kt < KT; kt++) {
        if (kt + 1 < KT) {
            loadA(kt + 1, (kt + 1) & 1);
            loadB(kt + 1, (kt + 1) & 1);
            cp_commit();
            CP_WAIT(1);
        } else {
            CP_WAIT(0);
        }
        __syncthreads();
        const float* As  = sm + (kt & 1) * STAGE;
        const float* Bsm = As + A_SZ;
        #pragma unroll
        for (int kk4 = 0; kk4 < 4; kk4++) {
            const int kk = kk4 * 8;
            uint32_t a[4][4], b[4][2];
            #pragma unroll
            for (int mi = 0; mi < 4; mi++) {
                int base = (wm0 + mi * 16 + r) * LDAS + kk + c4;
                a[mi][0] = f2tf32(As[base]);
                a[mi][1] = f2tf32(As[base + 8 * LDAS]);
                a[mi][2] = f2tf32(As[base + 4]);
                a[mi][3] = f2tf32(As[base + 8 * LDAS + 4]);
            }
            #pragma unroll
            for (int ni = 0; ni < 4; ni++) {
                int bb = (kk + c4) * LDBS + wn0 + ni * 8 + r;
                b[ni][0] = f2tf32(Bsm[bb]);
                b[ni][1] = f2tf32(Bsm[bb + 4 * LDBS]);
            }
            #pragma unroll
            for (int mi = 0; mi < 4; mi++)
                #pragma unroll
                for (int ni = 0; ni < 4; ni++)
                    mma_tf32(acc[mi][ni], a[mi], b[ni]);
        }
        __syncthreads();
    }

    #pragma unroll
    for (int mi = 0; mi < 4; mi++)
        #pragma unroll
        for (int ni = 0; ni < 4; ni++) {
            int row0 = m0 + wm0 + mi * 16 + r;
            int col0 = n0 + wn0 + ni * 8 + c4 * 2;
            #pragma unroll
            for (int h = 0; h < 2; h++) {
                int row = row0 + h * 8;
                #pragma unroll
                for (int q = 0; q < 2; q++) {
                    int col = col0 + q;
                    if (col < N)
                        C[(size_t)row * ldc + col] =
                            fmaxf(acc[mi][ni][h * 2 + q] + bias[col], 0.f);
                }
            }
        }
}

// ---------------------------------------------------------------------------
// transpose feat [8192, 343] -> featT [384, 8192], RNA-rounded, k-permuted,
// zero-padded rows 343..383.
// ---------------------------------------------------------------------------
__global__ void transpose_feat(const float* __restrict__ in,
                               float* __restrict__ out)
{
    __shared__ float t[32][33];
    int x  = blockIdx.x * 32 + threadIdx.x;   // n index (0..383)
    int y0 = blockIdx.y * 32;                 // k base
    #pragma unroll
    for (int j = threadIdx.y; j < 32; j += 8)
        t[j][threadIdx.x] = (x < IND) ? in[(size_t)(y0 + j) * IND + x] : 0.f;
    __syncthreads();
    int k  = y0 + threadIdx.x;
    int o  = k & 7;
    int kp = (k & ~7) | ((o < 4) ? (2 * o) : (2 * (o - 4) + 1));
    int n0 = blockIdx.x * 32;
    #pragma unroll
    for (int j = threadIdx.y; j < 32; j += 8)
        out[(size_t)(n0 + j) * NN + kp] = rna_f(t[threadIdx.x][j]);
}

// ---------------------------------------------------------------------------
// LayerNorm(1000) + head, one warp per row.
// ---------------------------------------------------------------------------
__global__ __launch_bounds__(256)
void ln_head_kernel(const float* __restrict__ h,
                    const float* __restrict__ gamma,
                    const float* __restrict__ beta,
                    const float* __restrict__ Wm,
                    const float* __restrict__ bm,
                    float* __restrict__ out)
{
    const int row  = blockIdx.x * 8 + threadIdx.y;
    if (row >= NN) return;
    const int lane = threadIdx.x;
    const float* hr = h + (size_t)row * HPAD;

    float v[32];
    float s = 0.f, ss = 0.f;
    #pragma unroll
    for (int i = 0; i < 32; i++) {
        int n = lane + 32 * i;
        float x = (n < HIDD) ? hr[n] : 0.f;
        v[i] = x; s += x; ss += x * x;
    }
    #pragma unroll
    for (int off = 16; off > 0; off >>= 1) {
        s  += __shfl_xor_sync(0xFFFFFFFF, s,  off);
        ss += __shfl_xor_sync(0xFFFFFFFF, ss, off);
    }
    const float mu   = s * (1.0f / HIDD);
    const float var  = ss * (1.0f / HIDD) - mu * mu;
    const float rinv = rsqrtf(var + EPS);

    float acc[OUTD] = {0.f, 0.f, 0.f, 0.f};
    #pragma unroll
    for (int i = 0; i < 32; i++) {
        int n = lane + 32 * i;
        if (n < HIDD) {
            float xn = (v[i] - mu) * rinv * gamma[n] + beta[n];
            #pragma unroll
            for (int o = 0; o < OUTD; o++)
                acc[o] = fmaf(xn, Wm[n * OUTD + o], acc[o]);
        }
    }
    #pragma unroll
    for (int o = 0; o < OUTD; o++) {
        #pragma unroll
        for (int off = 16; off > 0; off >>= 1)
            acc[o] += __shfl_xor_sync(0xFFFFFFFF, acc[o], off);
    }
    if (lane == 0) {
        #pragma unroll
        for (int o = 0; o < OUTD; o++)
            out[(size_t)row * OUTD + o] = acc[o] + bm[o];
    }
}

// ---------------------------------------------------------------------------
extern "C" void kernel_launch(void* const* d_in, const int* in_sizes, int n_in,
                              void* d_out, int out_size)
{
    const float* adj   = (const float*)d_in[0];
    const float* feat  = (const float*)d_in[1];
    const float* W1    = (const float*)d_in[2];
    const float* b1    = (const float*)d_in[3];
    const float* gamma = (const float*)d_in[4];
    const float* beta  = (const float*)d_in[5];
    const float* Wm    = (const float*)d_in[6];
    const float* bm    = (const float*)d_in[7];
    float* out = (float*)d_out;

    float *featT, *Yb, *h1;
    cudaGetSymbolAddress((void**)&featT, g_featT);
    cudaGetSymbolAddress((void**)&Yb,    g_Y);
    cudaGetSymbolAddress((void**)&h1,    g_h1);

    cudaFuncSetAttribute(gemmA, cudaFuncAttributeMaxDynamicSharedMemorySize, GA_SMEM);
    cudaFuncSetAttribute(gemmB, cudaFuncAttributeMaxDynamicSharedMemorySize, GB_SMEM);

    // featT = RNA(feat)^T, k-permuted, zero-padded
    {
        dim3 block(32, 8), grid(NPAD / 32, NN / 32);
        transpose_feat<<<grid, block>>>(feat, featT);
    }

    // GEMM_A: Y = adj @ feat   (128 CTAs, single wave)
    gemmA<<<NN / 64, 512, GA_SMEM>>>(adj, featT, Yb);

    // GEMM_B: h1 = relu(Y @ W1 + b1)
    {
        dim3 grid((HIDD + BN - 1) / BN, NN / BM);
        gemmB<<<grid, 256, GB_SMEM>>>(Yb, W1, b1, h1,
                                      NN, HIDD, IND, NPAD, HIDD, HPAD);
    }

    // LayerNorm + head
    {
        dim3 block(32, 8);
        ln_head_kernel<<<NN / 8, block>>>(h1, gamma, beta, Wm, bm, out);
    }
}